// round 4
// baseline (speedup 1.0000x reference)
#include <cuda_runtime.h>
#include <cuda_bf16.h>
#include <mma.h>
#include <math.h>

using namespace nvcuda;

#define B_  2
#define L_  2048
#define C_  1024
#define H_  16
#define HD_ 64
#define G_  32
#define CG_ 32          // channels per group
#define N3C (3 * C_)
#define ML  (B_ * L_)   // 4096 rows

typedef __nv_bfloat16 bf16;

// ---------------- scratch (static device globals; no allocation allowed) ----------------
__device__ float g_stats[B_ * G_ * 2];            // mu, rstd per (b,g)
__device__ bf16  g_xn_bf[(size_t)ML * C_];        // normalized input (bf16)   8 MB
__device__ float g_qkv[(size_t)ML * N3C];         // qkv projection (fp32)    48 MB
__device__ bf16  g_att_bf[(size_t)ML * C_];       // attention output (bf16)   8 MB
__device__ bf16  g_wq_bf[(size_t)C_ * N3C];       // qkv_w bf16                6 MB
__device__ bf16  g_wp_bf[(size_t)C_ * C_];        // proj_w bf16               2 MB

// ---------------- fp32 -> bf16 conversion (for weights) ----------------
__global__ void f2bf_kernel(const float* __restrict__ s, bf16* __restrict__ d, int n4) {
    int i = blockIdx.x * 256 + threadIdx.x;
    if (i < n4) {
        float4 v = ((const float4*)s)[i];
        __nv_bfloat162 a = __floats2bfloat162_rn(v.x, v.y);
        __nv_bfloat162 b = __floats2bfloat162_rn(v.z, v.w);
        ((__nv_bfloat162*)d)[2 * i]     = a;
        ((__nv_bfloat162*)d)[2 * i + 1] = b;
    }
}

// ---------------- kernel 1: GroupNorm statistics ----------------
__global__ void gn_stats_kernel(const float* __restrict__ x) {
    int bg = blockIdx.x;
    int b = bg / G_;
    int g = bg % G_;
    const float* xp = x + (size_t)b * L_ * C_ + g * CG_;

    float s = 0.f, s2 = 0.f;
    for (int i = threadIdx.x; i < L_ * CG_ / 4; i += 256) {
        int l = i >> 3;
        int c4 = (i & 7) * 4;
        float4 v = *(const float4*)(xp + (size_t)l * C_ + c4);
        s  += v.x + v.y + v.z + v.w;
        s2 += v.x * v.x + v.y * v.y + v.z * v.z + v.w * v.w;
    }
    #pragma unroll
    for (int o = 16; o > 0; o >>= 1) {
        s  += __shfl_down_sync(0xFFFFFFFFu, s, o);
        s2 += __shfl_down_sync(0xFFFFFFFFu, s2, o);
    }
    __shared__ float sh[2][8];
    int w = threadIdx.x >> 5, ln = threadIdx.x & 31;
    if (ln == 0) { sh[0][w] = s; sh[1][w] = s2; }
    __syncthreads();
    if (w == 0) {
        s  = (ln < 8) ? sh[0][ln] : 0.f;
        s2 = (ln < 8) ? sh[1][ln] : 0.f;
        #pragma unroll
        for (int o = 4; o > 0; o >>= 1) {
            s  += __shfl_down_sync(0xFFFFFFFFu, s, o);
            s2 += __shfl_down_sync(0xFFFFFFFFu, s2, o);
        }
        if (ln == 0) {
            const float inv_n = 1.0f / (float)(L_ * CG_);
            float mu  = s * inv_n;
            float var = s2 * inv_n - mu * mu;
            g_stats[bg * 2 + 0] = mu;
            g_stats[bg * 2 + 1] = rsqrtf(var + 1e-6f);
        }
    }
}

// ---------------- kernel 2: apply GroupNorm -> bf16 ----------------
__global__ void gn_apply_kernel(const float* __restrict__ x,
                                const float* __restrict__ gamma,
                                const float* __restrict__ beta) {
    size_t i = (size_t)blockIdx.x * blockDim.x + threadIdx.x;  // float4 index
    size_t base = i * 4;
    if (base >= (size_t)ML * C_) return;
    int c  = (int)(base % C_);
    int bl = (int)(base / C_);
    int b  = bl >> 11;           // L_ = 2048
    int g  = c >> 5;
    float mu = g_stats[(b * G_ + g) * 2 + 0];
    float rs = g_stats[(b * G_ + g) * 2 + 1];
    float4 xv = *(const float4*)(x + base);
    float4 gv = *(const float4*)(gamma + c);
    float4 bv = *(const float4*)(beta + c);
    float r0 = (xv.x - mu) * rs * gv.x + bv.x;
    float r1 = (xv.y - mu) * rs * gv.y + bv.y;
    float r2 = (xv.z - mu) * rs * gv.z + bv.z;
    float r3 = (xv.w - mu) * rs * gv.w + bv.w;
    ((__nv_bfloat162*)g_xn_bf)[2 * i]     = __floats2bfloat162_rn(r0, r1);
    ((__nv_bfloat162*)g_xn_bf)[2 * i + 1] = __floats2bfloat162_rn(r2, r3);
}

// ---------------- kernel 3/5: bf16 tensor-core GEMM 128x128, k-step 32 ----------------
// EPI 0: g_qkv = A @ W + bias                       (QKV, fp32 out)
// EPI 1: out   = (x + A @ W + bias) * rsqrt(2)      (proj + residual)
template <int EPI>
__global__ __launch_bounds__(256) void hgemm_kernel(
    const bf16*  __restrict__ A,       // [M x K] bf16 row-major
    const bf16*  __restrict__ W,       // [K x N] bf16 row-major
    const float* __restrict__ bias,    // [N]
    const float* __restrict__ resid,   // x for EPI==1
    float*       __restrict__ Cout,    // [M x N]
    int N, int K)
{
    __shared__ bf16 As[128][40];         // 128 x 32, pad to 40
    __shared__ bf16 Bs[32][136];         // 32 x 128, pad to 136
    __shared__ float esc[8][16][20];     // per-warp epilogue scratch

    int tid = threadIdx.x;
    int wid = tid >> 5;
    int lane = tid & 31;
    int warp_m = wid & 3;    // 0..3 -> 32-row strips
    int warp_n = wid >> 2;   // 0..1 -> 64-col strips
    int bm = blockIdx.y * 128;
    int bn = blockIdx.x * 128;

    wmma::fragment<wmma::accumulator, 16, 16, 16, float> acc[2][4];
    #pragma unroll
    for (int i = 0; i < 2; i++)
        #pragma unroll
        for (int j = 0; j < 4; j++) wmma::fill_fragment(acc[i][j], 0.f);

    // per-thread load coords
    int ar = tid >> 2;              // 0..63
    int ac = (tid & 3) * 8;         // 0,8,16,24
    int br = tid >> 4;              // 0..15
    int bc = (tid & 15) * 8;        // 0..120

    for (int k0 = 0; k0 < K; k0 += 32) {
        *(uint4*)&As[ar][ac]      = *(const uint4*)(A + (size_t)(bm + ar) * K + k0 + ac);
        *(uint4*)&As[ar + 64][ac] = *(const uint4*)(A + (size_t)(bm + ar + 64) * K + k0 + ac);
        *(uint4*)&Bs[br][bc]      = *(const uint4*)(W + (size_t)(k0 + br) * N + bn + bc);
        *(uint4*)&Bs[br + 16][bc] = *(const uint4*)(W + (size_t)(k0 + br + 16) * N + bn + bc);
        __syncthreads();

        #pragma unroll
        for (int ks = 0; ks < 2; ks++) {
            wmma::fragment<wmma::matrix_a, 16, 16, 16, bf16, wmma::row_major> af[2];
            wmma::load_matrix_sync(af[0], &As[warp_m * 32][ks * 16], 40);
            wmma::load_matrix_sync(af[1], &As[warp_m * 32 + 16][ks * 16], 40);
            #pragma unroll
            for (int j = 0; j < 4; j++) {
                wmma::fragment<wmma::matrix_b, 16, 16, 16, bf16, wmma::row_major> bfd;
                wmma::load_matrix_sync(bfd, &Bs[ks * 16][warp_n * 64 + j * 16], 136);
                wmma::mma_sync(acc[0][j], af[0], bfd, acc[0][j]);
                wmma::mma_sync(acc[1][j], af[1], bfd, acc[1][j]);
            }
        }
        __syncthreads();
    }

    // epilogue: per-warp scratch -> bias (+ residual) -> global
    const float rsqrt2 = 0.70710678118654752f;
    int er = lane >> 1;              // 0..15
    int ec = (lane & 1) * 8;         // 0 or 8
    #pragma unroll
    for (int i = 0; i < 2; i++) {
        #pragma unroll
        for (int j = 0; j < 4; j++) {
            wmma::store_matrix_sync(&esc[wid][0][0], acc[i][j], 20, wmma::mem_row_major);
            __syncwarp();
            int grow = bm + warp_m * 32 + i * 16 + er;
            int gcol = bn + warp_n * 64 + j * 16 + ec;
            float4 v0 = *(float4*)&esc[wid][er][ec];
            float4 v1 = *(float4*)&esc[wid][er][ec + 4];
            float4 bb0 = *(const float4*)(bias + gcol);
            float4 bb1 = *(const float4*)(bias + gcol + 4);
            v0.x += bb0.x; v0.y += bb0.y; v0.z += bb0.z; v0.w += bb0.w;
            v1.x += bb1.x; v1.y += bb1.y; v1.z += bb1.z; v1.w += bb1.w;
            if (EPI == 1) {
                float4 rv0 = *(const float4*)(resid + (size_t)grow * N + gcol);
                float4 rv1 = *(const float4*)(resid + (size_t)grow * N + gcol + 4);
                v0.x = (v0.x + rv0.x) * rsqrt2; v0.y = (v0.y + rv0.y) * rsqrt2;
                v0.z = (v0.z + rv0.z) * rsqrt2; v0.w = (v0.w + rv0.w) * rsqrt2;
                v1.x = (v1.x + rv1.x) * rsqrt2; v1.y = (v1.y + rv1.y) * rsqrt2;
                v1.z = (v1.z + rv1.z) * rsqrt2; v1.w = (v1.w + rv1.w) * rsqrt2;
            }
            *(float4*)(Cout + (size_t)grow * N + gcol)     = v0;
            *(float4*)(Cout + (size_t)grow * N + gcol + 4) = v1;
            __syncwarp();
        }
    }
}

// ---------------- kernel 4: flash attention (fp32 compute, bf16 out) ----------------
__global__ __launch_bounds__(128) void flash_kernel() {
    __shared__ float Ks[32 * 64];
    __shared__ float Vs[32 * 64];

    int bh = blockIdx.y;
    int b = bh >> 4;
    int h = bh & 15;
    int tid = threadIdx.x;
    int qrow = blockIdx.x * 128 + tid;

    const float* base = g_qkv + (size_t)b * L_ * N3C;
    const float* qptr = base + (size_t)qrow * N3C + h * (3 * HD_);
    const float* kbase = base + h * (3 * HD_) + HD_;
    const float* vbase = base + h * (3 * HD_) + 2 * HD_;

    float q[HD_];
    #pragma unroll
    for (int d4 = 0; d4 < HD_ / 4; d4++) {
        float4 t = *(const float4*)(qptr + d4 * 4);
        q[4 * d4 + 0] = t.x * 0.125f;
        q[4 * d4 + 1] = t.y * 0.125f;
        q[4 * d4 + 2] = t.z * 0.125f;
        q[4 * d4 + 3] = t.w * 0.125f;
    }
    float o[HD_];
    #pragma unroll
    for (int d = 0; d < HD_; d++) o[d] = 0.f;
    float m = -1e30f, l = 0.f;

    for (int kb = 0; kb < L_ / 32; kb++) {
        __syncthreads();
        #pragma unroll
        for (int t = 0; t < 4; t++) {
            int idx = t * 128 + tid;
            int r = idx >> 4;
            int c4 = (idx & 15) * 4;
            size_t goff = (size_t)(kb * 32 + r) * N3C + c4;
            *(float4*)&Ks[r * 64 + c4] = *(const float4*)(kbase + goff);
            *(float4*)&Vs[r * 64 + c4] = *(const float4*)(vbase + goff);
        }
        __syncthreads();

        float s[32];
        #pragma unroll
        for (int j = 0; j < 32; j++) {
            float acc = 0.f;
            #pragma unroll
            for (int d = 0; d < HD_; d++) acc += q[d] * Ks[j * 64 + d];
            s[j] = acc;
        }
        float mnew = m;
        #pragma unroll
        for (int j = 0; j < 32; j++) mnew = fmaxf(mnew, s[j]);
        float corr = __expf(m - mnew);
        l *= corr;
        #pragma unroll
        for (int d = 0; d < HD_; d++) o[d] *= corr;
        #pragma unroll
        for (int j = 0; j < 32; j++) {
            float p = __expf(s[j] - mnew);
            l += p;
            #pragma unroll
            for (int d = 0; d < HD_; d++) o[d] += p * Vs[j * 64 + d];
        }
        m = mnew;
    }

    float inv = 1.f / l;
    bf16* op = g_att_bf + (size_t)(b * L_ + qrow) * C_ + h * HD_;
    #pragma unroll
    for (int d2 = 0; d2 < HD_ / 2; d2++) {
        ((__nv_bfloat162*)op)[d2] =
            __floats2bfloat162_rn(o[2 * d2] * inv, o[2 * d2 + 1] * inv);
    }
}

// ---------------- launcher ----------------
extern "C" void kernel_launch(void* const* d_in, const int* in_sizes, int n_in,
                              void* d_out, int out_size) {
    const float* x        = (const float*)d_in[0];
    const float* gn_scale = (const float*)d_in[1];
    const float* gn_bias  = (const float*)d_in[2];
    const float* qkv_w    = (const float*)d_in[3];
    const float* qkv_b    = (const float*)d_in[4];
    const float* proj_w   = (const float*)d_in[5];
    const float* proj_b   = (const float*)d_in[6];
    float* out = (float*)d_out;

    // 0) convert weights to bf16 (device globals referenced inside kernels)
    {
        // need device addresses for dst: use kernels writing to globals directly
        // via small wrappers below (templated on dst)
    }
    // weight conversion into device globals: launch with dst resolved on device
    // (use lambdas via separate kernels to avoid cudaGetSymbolAddress)
    extern __global__ void f2bf_wq_kernel(const float*, int);
    extern __global__ void f2bf_wp_kernel(const float*, int);

    {
        int n4 = C_ * N3C / 4;
        f2bf_wq_kernel<<<(n4 + 255) / 256, 256>>>(qkv_w, n4);
    }
    {
        int n4 = C_ * C_ / 4;
        f2bf_wp_kernel<<<(n4 + 255) / 256, 256>>>(proj_w, n4);
    }

    // 1) GroupNorm stats
    gn_stats_kernel<<<B_ * G_, 256>>>(x);

    // 2) apply GroupNorm -> bf16
    {
        int total4 = ML * C_ / 4;
        gn_apply_kernel<<<(total4 + 255) / 256, 256>>>(x, gn_scale, gn_bias);
    }

    // 3) QKV GEMM (bf16 tensor cores): [4096,1024] x [1024,3072]
    {
        dim3 grid(N3C / 128, ML / 128);
        hgemm_kernel<0><<<grid, 256>>>(g_xn_bf, g_wq_bf, qkv_b, nullptr, g_qkv,
                                       N3C, C_);
    }

    // 4) flash attention
    {
        dim3 grid(L_ / 128, B_ * H_);
        flash_kernel<<<grid, 128>>>();
    }

    // 5) proj GEMM + residual (bf16 tensor cores)
    {
        dim3 grid(C_ / 128, ML / 128);
        hgemm_kernel<1><<<grid, 256>>>(g_att_bf, g_wp_bf, proj_b, x, out,
                                       C_, C_);
    }
}

// weight-conversion wrappers (write device globals directly; no symbol lookup)
__global__ void f2bf_wq_kernel(const float* __restrict__ s, int n4) {
    int i = blockIdx.x * 256 + threadIdx.x;
    if (i < n4) {
        float4 v = ((const float4*)s)[i];
        ((__nv_bfloat162*)g_wq_bf)[2 * i]     = __floats2bfloat162_rn(v.x, v.y);
        ((__nv_bfloat162*)g_wq_bf)[2 * i + 1] = __floats2bfloat162_rn(v.z, v.w);
    }
}
__global__ void f2bf_wp_kernel(const float* __restrict__ s, int n4) {
    int i = blockIdx.x * 256 + threadIdx.x;
    if (i < n4) {
        float4 v = ((const float4*)s)[i];
        ((__nv_bfloat162*)g_wp_bf)[2 * i]     = __floats2bfloat162_rn(v.x, v.y);
        ((__nv_bfloat162*)g_wp_bf)[2 * i + 1] = __floats2bfloat162_rn(v.z, v.w);
    }
}